// round 17
// baseline (speedup 1.0000x reference)
#include <cuda_runtime.h>
#include <math.h>

// Problem constants
#define BB      128
#define CC      3
#define HH      224
#define PN      14          // patches per side
#define PS      16          // patch size
#define NP      196         // PN*PN
#define DD      768
#define NC      1000
#define TOPK    20
#define KDIM    588         // C*NP
#define NPART   16          // partials for patch_grad reduction (8 batches each)
#define SPLITK  12
#define KT      49          // KDIM / SPLITK

// GEMM tile
#define BM 32
#define BN 64
#define BMP 36              // BM + 4 pad

// Single-kernel bid layout: [pool][gemm][grad][v][softmax]
#define POOL_T    5418      // 129 * 3 * 14
#define GEMM_B    768       // 16 n * 4 m * 12 z
#define GRAD_T    3136      // 196 * 16
#define VB        8
#define PROD_T    (GEMM_B + VB)          // 776
#define GEMM_OFF  POOL_T                 // 5418
#define GRAD_OFF  (GEMM_OFF + GEMM_B)    // 6186
#define V_OFF     (GRAD_OFF + GRAD_T)    // 9322
#define SM_OFF    (V_OFF + VB)           // 9330
#define TOTAL_B   (SM_OFF + BB)          // 9458

// -------- scratch (device globals; no runtime allocation) --------
__device__ float g_patch_partial[NP * NPART];
__device__ float g_attack_pooled[KDIM];
__device__ float g_pooled_in[BB * KDIM];
__device__ float g_logits_part[SPLITK][BB * NC];
__device__ float g_v[NC];
__device__ float g_probs_fallback[BB * NC];
__device__ float g_ce[BB];
// Counters: zero at module load; the LAST consumer resets them to zero at the
// end of every call -> every graph replay starts from a clean state.
__device__ int   g_c_pool;
__device__ int   g_c_grad;
__device__ int   g_c_prod;
__device__ int   g_ctr;

__device__ __forceinline__ float warpMax(float v) {
    #pragma unroll
    for (int o = 16; o > 0; o >>= 1) v = fmaxf(v, __shfl_xor_sync(0xffffffffu, v, o));
    return v;
}
__device__ __forceinline__ float warpSum(float v) {
    #pragma unroll
    for (int o = 16; o > 0; o >>= 1) v += __shfl_xor_sync(0xffffffffu, v, o);
    return v;
}

__global__ void __launch_bounds__(128, 8)
mega_kernel(const float* __restrict__ inputs,
            const float* __restrict__ attack_w,
            const float* __restrict__ patch_grad,
            const float* __restrict__ w_cls,
            const int*   __restrict__ targets,
            float* __restrict__ pdst,
            float* __restrict__ out, int loss_idx) {
    int bid = blockIdx.x;
    int t   = threadIdx.x;   // 0..127

    if (bid < POOL_T) {
        // ================= POOL: 16x16 means of inputs / attack_w ==========
        // block = one (bb, c, patch-row). 112 threads carry float2 column
        // pairs; threads 112-127 contribute zeros (full-mask shuffles).
        int bb  = bid / (CC * PN);
        int rem = bid % (CC * PN);
        int c   = rem / PN;
        int px  = rem % PN;
        const float* src = (bb < BB)
            ? inputs   + ((size_t)(bb * CC + c) * HH + px * PS) * HH
            : attack_w + ((size_t)c * HH + px * PS) * HH;
        float acc = 0.f;
        if (t < 112) {
            const float2* s2 = (const float2*)src;   // 112 float2 per row
            float ax = 0.f, ay = 0.f;
            #pragma unroll
            for (int r = 0; r < PS; ++r) {
                float2 v = s2[r * 112 + t];
                ax += v.x; ay += v.y;
            }
            acc = ax + ay;
        }
        // reduce within groups of 8 lanes (one group per output patch)
        #pragma unroll
        for (int off = 4; off > 0; off >>= 1)
            acc += __shfl_down_sync(0xffffffffu, acc, off, 8);
        if (t < 112 && (t & 7) == 0) {
            int iy  = t >> 3;                       // 0..13
            float v = acc * (1.0f / 256.0f);
            int idx = c * NP + px * PN + iy;
            if (bb < BB) g_pooled_in[bb * KDIM + idx] = v;
            else         g_attack_pooled[idx]          = v;
        }
        __syncthreads();
        if (t == 0) { __threadfence(); atomicAdd(&g_c_pool, 1); }
    } else if (bid < GRAD_OFF) {
        // ================= GEMM: split-K-12, BM32 x BN64 x KT49 ============
        __shared__ float sA[KT][BMP];
        __shared__ float sW[KT][BN];
        int gb = bid - GEMM_OFF;
        int n0 = (gb & 15) * BN;
        int m0 = ((gb >> 4) & 3) * BM;
        int z  = gb >> 6;              // 0..11
        int k0 = z * KT;
        int tn4 = (t & 15) * 4;
        int tm4 = (t >> 4) * 4;

        // Pre-fill sW (w_cls independent of pool) BEFORE waiting.
        for (int i = t; i < KT * BN; i += 128) {
            int kk = i >> 6;
            int n  = i & 63;
            int gn = n0 + n;
            sW[kk][n] = (gn < NC) ? w_cls[(size_t)(k0 + kk) * NC + gn] : 0.0f;
        }
        // Wait for pooled inputs.
        if (t == 0) {
            volatile int* vp = &g_c_pool;
            while (*vp < POOL_T) __nanosleep(128);
        }
        __syncthreads();
        __threadfence();
        for (int i = t; i < BM * KT; i += 128) {
            int m = i / KT;
            int k = i - m * KT;
            sA[k][m] = g_pooled_in[(m0 + m) * KDIM + k0 + k];
        }
        __syncthreads();

        float acc[4][4];
        #pragma unroll
        for (int r = 0; r < 4; ++r)
            #pragma unroll
            for (int c2 = 0; c2 < 4; ++c2) acc[r][c2] = 0.f;

        #pragma unroll 7
        for (int k = 0; k < KT; ++k) {
            float4 a = *(const float4*)&sA[k][tm4];
            float4 w = *(const float4*)&sW[k][tn4];
            acc[0][0] += a.x * w.x; acc[0][1] += a.x * w.y;
            acc[0][2] += a.x * w.z; acc[0][3] += a.x * w.w;
            acc[1][0] += a.y * w.x; acc[1][1] += a.y * w.y;
            acc[1][2] += a.y * w.z; acc[1][3] += a.y * w.w;
            acc[2][0] += a.z * w.x; acc[2][1] += a.z * w.y;
            acc[2][2] += a.z * w.z; acc[2][3] += a.z * w.w;
            acc[3][0] += a.w * w.x; acc[3][1] += a.w * w.y;
            acc[3][2] += a.w * w.z; acc[3][3] += a.w * w.w;
        }

        float* dst = g_logits_part[z];
        #pragma unroll
        for (int r = 0; r < 4; ++r) {
            int m = m0 + tm4 + r;
            #pragma unroll
            for (int j = 0; j < 4; ++j) {
                int n = n0 + tn4 + j;
                if (n < NC) dst[m * NC + n] = acc[r][j];
            }
        }
        __syncthreads();
        if (t == 0) { __threadfence(); atomicAdd(&g_c_prod, 1); }
    } else if (bid < V_OFF) {
        // ================= GRAD: reduce patch_grad over (8 batches, dim) ===
        int gid  = bid - GRAD_OFF;
        int p    = gid >> 4;
        int part = gid & 15;
        int b0   = part * (BB / NPART);
        float acc = 0.f;
        #pragma unroll
        for (int bi = 0; bi < BB / NPART; ++bi) {
            const float4* row = reinterpret_cast<const float4*>(
                patch_grad + ((size_t)(b0 + bi) * NP + p) * DD);  // 192 float4
            float4 v = row[t];
            acc += (v.x + v.y) + (v.z + v.w);
            if (t < 64) {
                float4 v2 = row[t + 128];
                acc += (v2.x + v2.y) + (v2.z + v2.w);
            }
        }
        acc = warpSum(acc);
        __shared__ float ws[4];
        if ((t & 31) == 0) ws[t >> 5] = acc;
        __syncthreads();
        if (t == 0) {
            float s = ((ws[0] + ws[1]) + (ws[2] + ws[3]));
            g_patch_partial[p * NPART + part] = s;
            __threadfence();
            atomicAdd(&g_c_grad, 1);
        }
    } else if (bid < SM_OFF) {
        // ================= V: top-k mask + masked GEMV =====================
        int vb = bid - V_OFF;   // 0..7
        __shared__ float         sv[NP];
        __shared__ unsigned char smask[NP];
        __shared__ int           plist[TOPK];
        if (t == 0) {
            volatile int* vg = &g_c_grad;
            while (*vg < GRAD_T) __nanosleep(256);
            volatile int* vp = &g_c_pool;
            while (*vp < POOL_T) __nanosleep(256);
        }
        __syncthreads();
        __threadfence();
        for (int i = t; i < NP; i += 128) {
            float v = 0.f;
            #pragma unroll
            for (int q = 0; q < NPART; ++q) v += g_patch_partial[i * NPART + q];
            sv[i] = v;
        }
        __syncthreads();
        // rank-based top-20; ties broken by lower index (jax.lax.top_k order)
        for (int i = t; i < NP; i += 128) {
            float v = sv[i];
            int rank = 0;
            for (int j = 0; j < NP; ++j) {
                float u = sv[j];
                rank += (u > v) || (u == v && j < i);
            }
            smask[i] = (rank < TOPK) ? 1 : 0;
        }
        __syncthreads();
        if (t == 0) {                          // deterministic ascending list
            int cnt = 0;
            for (int p = 0; p < NP; ++p)
                if (smask[p] && cnt < TOPK) plist[cnt++] = p;
        }
        __syncthreads();
        int n = vb * 125 + t;                  // 8 blocks x 125 cols = 1000
        if (t < 125) {
            float acc = 0.f;
            #pragma unroll 2
            for (int i = 0; i < TOPK; ++i) {
                int p = plist[i];
                #pragma unroll
                for (int c = 0; c < CC; ++c) {
                    int k = c * NP + p;
                    acc += g_attack_pooled[k] * w_cls[(size_t)k * NC + n];
                }
            }
            g_v[n] = acc;
        }
        __syncthreads();
        if (t == 0) { __threadfence(); atomicAdd(&g_c_prod, 1); }
    } else {
        // ================= SOFTMAX + CE per batch row ======================
        int b = bid - SM_OFF;          // 0..127
        int w = t >> 5;
        __shared__ float red[4];
        __shared__ float ptgt;
        __shared__ int   slast;

        if (t == 0) {
            volatile int* dp = &g_c_prod;
            while (*dp < PROD_T) __nanosleep(256);
        }
        __syncthreads();
        __threadfence();

        float l[8];
        float m = -INFINITY;
        #pragma unroll
        for (int i = 0; i < 8; ++i) {
            int j = t + i * 128;
            if (j < NC) {
                size_t o = (size_t)b * NC + j;
                float s = g_v[j];
                #pragma unroll
                for (int zz = 0; zz < SPLITK; ++zz)   // fixed order: deterministic
                    s += g_logits_part[zz][o];
                l[i] = s;
                m = fmaxf(m, l[i]);
            } else l[i] = -INFINITY;
        }
        m = warpMax(m);
        if ((t & 31) == 0) red[w] = m;
        __syncthreads();
        float rowmax = fmaxf(fmaxf(red[0], red[1]), fmaxf(red[2], red[3]));
        __syncthreads();

        float e[8]; float ssum = 0.f;
        #pragma unroll
        for (int i = 0; i < 8; ++i) {
            int j = t + i * 128;
            e[i] = (j < NC) ? __expf(l[i] - rowmax) : 0.f;
            ssum += e[i];
        }
        ssum = warpSum(ssum);
        if ((t & 31) == 0) red[w] = ssum;
        __syncthreads();
        float tot = ((red[0] + red[1]) + (red[2] + red[3]));
        float inv = 1.0f / tot;
        __syncthreads();

        int tgt = targets[b];
        float s2 = 0.f;
        #pragma unroll
        for (int i = 0; i < 8; ++i) {
            int j = t + i * 128;
            if (j < NC) {
                float p = e[i] * inv;
                pdst[(size_t)b * NC + j] = p;
                if (j == tgt) ptgt = p;
                // exp(p), p in (0,1]: degree-4 Taylor (FMA pipe, not MUFU)
                float q = fmaf(p, 1.0f / 24.0f, 1.0f / 6.0f);
                q = fmaf(p, q, 0.5f);
                q = fmaf(p, q, 1.0f);
                q = fmaf(p, q, 1.0f);
                s2 += q;
            }
        }
        s2 = warpSum(s2);
        if ((t & 31) == 0) red[w] = s2;
        __syncthreads();
        if (t == 0) {
            float tot2 = ((red[0] + red[1]) + (red[2] + red[3]));
            g_ce[b] = logf(tot2) - ptgt;
            __threadfence();
            int done = atomicAdd(&g_ctr, 1);
            slast = (done == BB - 1) ? 1 : 0;
        }
        __syncthreads();
        if (slast) {
            if (t < 32) {
                __threadfence();
                float s = 0.f;
                #pragma unroll
                for (int i = 0; i < 4; ++i) s += g_ce[t * 4 + i];
                #pragma unroll
                for (int off = 16; off > 0; off >>= 1)
                    s += __shfl_down_sync(0xffffffffu, s, off);
                if (t == 0) {
                    if (loss_idx >= 0) out[loss_idx] = -(s * (1.0f / BB));
                    // reset counters for the next graph replay (deterministic)
                    g_c_pool = 0; g_c_grad = 0; g_c_prod = 0; g_ctr = 0;
                }
            }
        }
    }
}

// ============================================================================
extern "C" void kernel_launch(void* const* d_in, const int* in_sizes, int n_in,
                              void* d_out, int out_size) {
    const float* inputs     = (const float*)d_in[0];   // [128,3,224,224]
    const float* patch_grad = (const float*)d_in[1];   // [128,196,768]
    const float* attack_w   = (const float*)d_in[2];   // [3,224,224]
    const float* w_cls      = (const float*)d_in[3];   // [588,1000]
    const int*   targets    = (const int*)d_in[4];     // [128]
    float* out = (float*)d_out;

    (void)in_sizes; (void)n_in;

    float* pdst = out;
    if (out_size < BB * NC) {
        float* fb = nullptr;
        cudaGetSymbolAddress((void**)&fb, g_probs_fallback);
        pdst = fb;
    }
    int loss_idx = -1;
    if (out_size >= BB * NC + 1)      loss_idx = BB * NC;
    else if (out_size == 1)           loss_idx = 0;

    mega_kernel<<<TOTAL_B, 128>>>(inputs, attack_w, patch_grad, w_cls,
                                  targets, pdst, out, loss_idx);
}